// round 10
// baseline (speedup 1.0000x reference)
#include <cuda_runtime.h>
#include <cuda_bf16.h>
#include <math.h>

// Problem constants
#define BATCH   512
#define DIM     256
#define NTREES  512
#define DEPTH   6
#define UNITS   3
#define NLEAVES 64
#define NCOLS   (NTREES * DEPTH)   // 3072 sparsemax columns
#define BT      32                 // forest batch tile
#define NT      8                  // forest tree tile
#define MAXK    64                 // cap on sparsemax support size (typ. 5-9)

// -------- device scratch (no dynamic allocation allowed) --------
__device__ float g_xT[DIM * BATCH];       // transposed x: (DIM, BATCH)
__device__ float g_fslT[NCOLS * DIM];     // transposed fsl: (col, i)
__device__ float g_gate[NCOLS * BATCH];   // gate values, layout (col, b)

// ============================================================================
// Kernel 0: tiled transposes (pure coalesced bandwidth).
//  blocks [0, 768): fsl (256 i, 3072 col) -> fslT (col, i), 32x32 tiles.
//  blocks [768, 896): x (512 b, 256 i)    -> xT (i, b),     32x32 tiles.
// ============================================================================
__global__ void __launch_bounds__(256)
transpose_kernel(const float* __restrict__ x,
                 const float* __restrict__ fsl)
{
    __shared__ float tile[32][33];
    const int bid = blockIdx.x;
    const int tid = threadIdx.x;
    const int tx = tid & 31;
    const int ty = tid >> 5;          // 0..7

    if (bid < 768) {
        const int ct = bid % 96;
        const int it = bid / 96;
        #pragma unroll
        for (int r = 0; r < 4; r++) {
            int row = ty + r * 8;
            tile[row][tx] = fsl[(it * 32 + row) * NCOLS + ct * 32 + tx];
        }
        __syncthreads();
        #pragma unroll
        for (int r = 0; r < 4; r++) {
            int row = ty + r * 8;
            g_fslT[(ct * 32 + row) * DIM + it * 32 + tx] = tile[tx][row];
        }
    } else {
        const int t  = bid - 768;
        const int bt = t & 15;
        const int it = t >> 4;
        #pragma unroll
        for (int r = 0; r < 4; r++) {
            int row = ty + r * 8;
            tile[row][tx] = x[(bt * 32 + row) * DIM + it * 32 + tx];
        }
        __syncthreads();
        #pragma unroll
        for (int r = 0; r < 4; r++) {
            int row = ty + r * 8;
            g_xT[(it * 32 + row) * BATCH + bt * 32 + tx] = tile[tx][row];
        }
    }
}

// ============================================================================
// Kernel 1: FUSED sparsemax + gate. Block = one column (3072 blocks, 256 thr).
//  1. z[tid] = fslT[col*256+tid]      (one coalesced 1KB read)
//  2. block-level Michelot projection, warm-started at tau0 = max(z)-1
//     (valid: tau* >= zmax-1) -> ~2-3 iterations, 2-level shfl+smem reduce
//  3. compact support into SMEM list (no gmem round-trip)
//  4. gate[col][b] = sparsemoid((sum_j w_j*xT[i_j][b] - th)*e^{-lt}), 2 b/thr
// ============================================================================
__global__ void __launch_bounds__(256)
gate_kernel(const float* __restrict__ th,   // (NTREES, DEPTH) == [col]
            const float* __restrict__ lt)   // (NTREES, DEPTH) == [col]
{
    const int col  = blockIdx.x;
    const int tid  = threadIdx.x;
    const int warp = tid >> 5;
    const int lane = tid & 31;

    __shared__ float  s_s[8];
    __shared__ int    s_ki[8];
    __shared__ float2 s_list[MAXK];   // (idx*BATCH as int bits, weight)
    __shared__ int    s_cnt;

    const float z = g_fslT[col * DIM + tid];

    // ---- block max -> warm start tau0 = max - 1 ----
    float m = z;
    #pragma unroll
    for (int o = 16; o > 0; o >>= 1)
        m = fmaxf(m, __shfl_xor_sync(0xffffffffu, m, o));
    if (lane == 0) s_s[warp] = m;
    __syncthreads();
    float mm = s_s[0];
    #pragma unroll
    for (int w = 1; w < 8; w++) mm = fmaxf(mm, s_s[w]);
    float tau = mm - 1.0f;
    __syncthreads();

    // ---- Michelot: tau <- (sum_{z>tau} z - 1)/k until support stable ----
    int k_prev = -1;
    #pragma unroll 1
    for (int it = 0; it < 12; it++) {
        float s = (z > tau) ? z : 0.0f;
        int   k = (z > tau) ? 1 : 0;
        #pragma unroll
        for (int o = 16; o > 0; o >>= 1) {
            s += __shfl_xor_sync(0xffffffffu, s, o);
            k += __shfl_xor_sync(0xffffffffu, k, o);
        }
        if (lane == 0) { s_s[warp] = s; s_ki[warp] = k; }
        __syncthreads();
        float S = 0.0f; int K = 0;
        #pragma unroll
        for (int w = 0; w < 8; w++) { S += s_s[w]; K += s_ki[w]; }
        __syncthreads();                  // guard smem reuse next iter
        if (K == k_prev) break;           // uniform across block
        k_prev = K;
        tau = (S - 1.0f) / (float)K;
    }

    // ---- compact support into smem ----
    const bool nz = (z > tau);
    const unsigned bm = __ballot_sync(0xffffffffu, nz);
    if (lane == 0) s_ki[warp] = __popc(bm);
    __syncthreads();
    int base = 0, total = 0;
    #pragma unroll
    for (int w = 0; w < 8; w++) {
        if (w < warp) base += s_ki[w];
        total += s_ki[w];
    }
    if (nz) {
        int pos = base + __popc(bm & ((1u << lane) - 1u));
        if (pos < MAXK)
            s_list[pos] = make_float2(__int_as_float(tid * BATCH), z - tau);
    }
    if (tid == 0) s_cnt = (total < MAXK) ? total : MAXK;
    __syncthreads();

    // ---- gate for two batch rows per thread ----
    const int   cnt = s_cnt;
    const float thv = __ldg(th + col);
    const float etv = __expf(-__ldg(lt + col));

    float f0 = 0.0f, f1 = 0.0f;
    int j = 0;
    #pragma unroll 1
    for (; j + 2 <= cnt; j += 2) {
        float2 e0 = s_list[j];
        float2 e1 = s_list[j + 1];
        int o0 = __float_as_int(e0.x);
        int o1 = __float_as_int(e1.x);
        float a0 = g_xT[o0 + tid];
        float a1 = g_xT[o0 + tid + 256];
        float b0 = g_xT[o1 + tid];
        float b1 = g_xT[o1 + tid + 256];
        f0 += e0.y * a0 + e1.y * b0;
        f1 += e0.y * a1 + e1.y * b1;
    }
    if (j < cnt) {
        float2 e = s_list[j];
        int o = __float_as_int(e.x);
        f0 += e.y * g_xT[o + tid];
        f1 += e.y * g_xT[o + tid + 256];
    }
    g_gate[col * BATCH + tid]       = __saturatef(0.5f * ((f0 - thv) * etv) + 0.5f);
    g_gate[col * BATCH + tid + 256] = __saturatef(0.5f * ((f1 - thv) * etv) + 0.5f);
}

// ============================================================================
// Kernel 2: tiled forest, coalesced output. Block = (32-b x 8-n) tile;
// 1024 blocks x 256 threads (grid-quantization fixed: ~7 blocks/SM).
// tx = b_local, ty = n_local. Gates read coalesced before the staging barrier;
// resp LDS reads warp-broadcast; results staged (stride 25, conflict-free)
// and written as contiguous 96B runs per batch row.
// ============================================================================
__global__ void __launch_bounds__(256)
forest_kernel(const float* __restrict__ resp,  // (NTREES, UNITS, NLEAVES)
              float* __restrict__ out)         // (BATCH, NTREES, UNITS)
{
    const int nt  = blockIdx.x & 63;      // 64 n-tiles
    const int btl = blockIdx.x >> 6;      // 16 b-tiles
    const int n0  = nt * NT;
    const int b0  = btl * BT;
    const int tid = threadIdx.x;
    const int tx  = tid & 31;             // b_local
    const int ty  = tid >> 5;             // n_local, 0..7

    const int b = b0 + tx;
    const int n = n0 + ty;

    // issue gate loads first (independent of smem staging)
    float g[DEPTH];
    #pragma unroll
    for (int d = 0; d < DEPTH; d++)
        g[d] = g_gate[(n * DEPTH + d) * BATCH + b];

    __shared__ float4 s_resp[NT * 48];            // 8 trees x 192 floats = 6 KB
    __shared__ float  s_out[BT][NT * UNITS + 1];  // 32 x 25, conflict-free

    s_resp[tid] = ((const float4*)resp)[n0 * 48 + tid];
    if (tid < NT * 48 - 256)
        s_resp[tid + 256] = ((const float4*)resp)[n0 * 48 + tid + 256];
    __syncthreads();

    // leaf prob factorization: p_c = qlo[c&7] * qhi[c>>3]
    float qlo[8], qhi[8];
    #pragma unroll
    for (int c = 0; c < 8; c++) {
        float p0 = (c & 1) ? (1.0f - g[0]) : g[0];
        float p1 = (c & 2) ? (1.0f - g[1]) : g[1];
        float p2 = (c & 4) ? (1.0f - g[2]) : g[2];
        qlo[c] = p0 * p1 * p2;
        float p3 = (c & 1) ? (1.0f - g[3]) : g[3];
        float p4 = (c & 2) ? (1.0f - g[4]) : g[4];
        float p5 = (c & 4) ? (1.0f - g[5]) : g[5];
        qhi[c] = p3 * p4 * p5;
    }

    // response contraction (smem reads broadcast across the warp)
    float acc0 = 0.0f, acc1 = 0.0f, acc2 = 0.0f;
    #pragma unroll
    for (int hi = 0; hi < 8; hi++) {
        const float qh = qhi[hi];
        #pragma unroll
        for (int u = 0; u < UNITS; u++) {
            float4 a = s_resp[ty * 48 + (u * NLEAVES + hi * 8) / 4];
            float4 c = s_resp[ty * 48 + (u * NLEAVES + hi * 8) / 4 + 1];
            float t = a.x * qlo[0] + a.y * qlo[1] + a.z * qlo[2] + a.w * qlo[3]
                    + c.x * qlo[4] + c.y * qlo[5] + c.z * qlo[6] + c.w * qlo[7];
            if (u == 0) acc0 += qh * t;
            else if (u == 1) acc1 += qh * t;
            else acc2 += qh * t;
        }
    }

    s_out[tx][ty * UNITS + 0] = acc0;
    s_out[tx][ty * UNITS + 1] = acc1;
    s_out[tx][ty * UNITS + 2] = acc2;
    __syncthreads();

    // coalesced write-out: per-b contiguous 24-float (96 B) runs
    #pragma unroll
    for (int r = 0; r < 3; r++) {
        int i   = tid + r * 256;                 // 0 .. 767
        int row = i / (NT * UNITS);              // b_local
        int c   = i % (NT * UNITS);
        out[(size_t)(b0 + row) * (NTREES * UNITS) + n0 * UNITS + c] = s_out[row][c];
    }
}

// ============================================================================
extern "C" void kernel_launch(void* const* d_in, const int* in_sizes, int n_in,
                              void* d_out, int out_size)
{
    const float* x    = (const float*)d_in[0];  // (512, 256)
    const float* fsl  = (const float*)d_in[1];  // (256, 512, 6)
    const float* th   = (const float*)d_in[2];  // (512, 6)
    const float* lt   = (const float*)d_in[3];  // (512, 6)
    const float* resp = (const float*)d_in[4];  // (512, 3, 64)
    float* out = (float*)d_out;                 // (512, 512, 3)

    transpose_kernel<<<896, 256>>>(x, fsl);
    gate_kernel<<<NCOLS, 256>>>(th, lt);
    forest_kernel<<<(BATCH / BT) * (NTREES / NT), 256>>>(resp, out);
}

// round 11
// speedup vs baseline: 1.1822x; 1.1822x over previous
#include <cuda_runtime.h>
#include <cuda_bf16.h>
#include <math.h>

// Problem constants
#define BATCH   512
#define DIM     256
#define NTREES  512
#define DEPTH   6
#define UNITS   3
#define NLEAVES 64
#define NCOLS   (NTREES * DEPTH)   // 3072 sparsemax columns
#define MAXC    64                 // max sparsemax support per column (padded)
#define BT      32                 // forest batch tile
#define NT      8                  // forest tree tile

// -------- device scratch (no dynamic allocation allowed) --------
__device__ float  g_xT[DIM * BATCH];       // transposed x: (DIM, BATCH)
__device__ float  g_fslT[NCOLS * DIM];     // transposed fsl: (col, i)
__device__ int    g_nnz[NCOLS];            // PADDED support size (multiple of 8)
__device__ float2 g_sel[NCOLS * MAXC];     // interleaved (idx*BATCH as int bits, weight)
__device__ float  g_gate[NCOLS * BATCH];   // gate values, layout (col, b)

// ============================================================================
// Kernel 0: tiled transposes (pure coalesced bandwidth).
//  blocks [0, 768): fsl (256 i, 3072 col) -> fslT (col, i), 32x32 tiles.
//  blocks [768, 896): x (512 b, 256 i)    -> xT (i, b),     32x32 tiles.
// ============================================================================
__global__ void __launch_bounds__(256)
transpose_kernel(const float* __restrict__ x,
                 const float* __restrict__ fsl)
{
    __shared__ float tile[32][33];
    const int bid = blockIdx.x;
    const int tid = threadIdx.x;
    const int tx = tid & 31;
    const int ty = tid >> 5;          // 0..7

    if (bid < 768) {
        const int ct = bid % 96;
        const int it = bid / 96;
        #pragma unroll
        for (int r = 0; r < 4; r++) {
            int row = ty + r * 8;
            tile[row][tx] = fsl[(it * 32 + row) * NCOLS + ct * 32 + tx];
        }
        __syncthreads();
        #pragma unroll
        for (int r = 0; r < 4; r++) {
            int row = ty + r * 8;
            g_fslT[(ct * 32 + row) * DIM + it * 32 + tx] = tile[tx][row];
        }
    } else {
        const int t  = bid - 768;
        const int bt = t & 15;
        const int it = t >> 4;
        #pragma unroll
        for (int r = 0; r < 4; r++) {
            int row = ty + r * 8;
            tile[row][tx] = x[(bt * 32 + row) * DIM + it * 32 + tx];
        }
        __syncthreads();
        #pragma unroll
        for (int r = 0; r < 4; r++) {
            int row = ty + r * 8;
            g_xT[(it * 32 + row) * BATCH + bt * 32 + tx] = tile[tx][row];
        }
    }
}

// ============================================================================
// Kernel 1: sparsemax, one warp per column, coalesced fslT loads.
// 384 blocks x 256 threads, warp-level only (no block syncs).
// Michelot warm-started at tau0 = max(z)-1 (valid: tau* >= zmax-1).
// Output list zero-padded to a multiple of 8.
// ============================================================================
__global__ void __launch_bounds__(256)
sparsemax_kernel()
{
    const int warp = threadIdx.x >> 5;
    const int lane = threadIdx.x & 31;
    const int col  = blockIdx.x * 8 + warp;

    float z[8];
    #pragma unroll
    for (int j = 0; j < 8; j++)
        z[j] = g_fslT[col * DIM + j * 32 + lane];

    float m = z[0];
    #pragma unroll
    for (int j = 1; j < 8; j++) m = fmaxf(m, z[j]);
    #pragma unroll
    for (int o = 16; o > 0; o >>= 1)
        m = fmaxf(m, __shfl_xor_sync(0xffffffffu, m, o));
    float tau = m - 1.0f;

    int k_prev = -1;
    #pragma unroll 1
    for (int it = 0; it < 16; it++) {
        float s = 0.0f;
        int   k = 0;
        #pragma unroll
        for (int j = 0; j < 8; j++)
            if (z[j] > tau) { s += z[j]; k++; }
        #pragma unroll
        for (int o = 16; o > 0; o >>= 1)
            s += __shfl_xor_sync(0xffffffffu, s, o);
        k = __reduce_add_sync(0xffffffffu, k);
        if (k == k_prev) break;
        k_prev = k;
        tau = (s - 1.0f) / (float)k;
    }

    int base = 0;
    #pragma unroll
    for (int j = 0; j < 8; j++) {
        const bool nz = (z[j] > tau);
        const unsigned mm = __ballot_sync(0xffffffffu, nz);
        if (nz) {
            int pos = base + __popc(mm & ((1u << lane) - 1u));
            if (pos < MAXC)
                g_sel[col * MAXC + pos] =
                    make_float2(__int_as_float((j * 32 + lane) * BATCH), z[j] - tau);
        }
        base += __popc(mm);
    }
    if (base > MAXC) base = MAXC;
    const int pad = (base + 7) & ~7;
    if (lane < pad - base)
        g_sel[col * MAXC + base + lane] = make_float2(__int_as_float(0), 0.0f);
    if (lane == 0) g_nnz[col] = pad;
}

// ============================================================================
// Kernel 2: gate[col][b] = sparsemoid((sum_j w_j*xT[idx_j][b] - th)*e^{-lt}).
// One block per column (3072 blocks, 256 threads, 2 b's per thread).
// Branchless 8-entry steps: 16 independent xT loads in flight.
// ============================================================================
__global__ void __launch_bounds__(256)
fv_kernel(const float* __restrict__ th,
          const float* __restrict__ lt)
{
    const int col = blockIdx.x;
    const int tid = threadIdx.x;
    const int cnt = g_nnz[col];           // multiple of 8
    const float2* __restrict__ lst = g_sel + col * MAXC;

    const float thv = __ldg(th + col);
    const float etv = __expf(-__ldg(lt + col));

    float f0 = 0.0f, f1 = 0.0f;
    #pragma unroll 1
    for (int j = 0; j < cnt; j += 8) {
        float2 e[8];
        #pragma unroll
        for (int q = 0; q < 8; q++) e[q] = __ldg(lst + j + q);
        float v0[8], v1[8];
        #pragma unroll
        for (int q = 0; q < 8; q++) {
            int o = __float_as_int(e[q].x);
            v0[q] = g_xT[o + tid];
            v1[q] = g_xT[o + tid + 256];
        }
        #pragma unroll
        for (int q = 0; q < 8; q++) {
            f0 += e[q].y * v0[q];
            f1 += e[q].y * v1[q];
        }
    }
    g_gate[col * BATCH + tid]       = __saturatef(0.5f * ((f0 - thv) * etv) + 0.5f);
    g_gate[col * BATCH + tid + 256] = __saturatef(0.5f * ((f1 - thv) * etv) + 0.5f);
}

// ============================================================================
// Kernel 3: tiled forest, coalesced output. Block = (32-b x 8-n) tile;
// 1024 blocks x 256 threads (fixes R9's grid quantization: ~7 blocks/SM).
// tx = b_local, ty = n_local. Gates read coalesced before the staging barrier;
// resp LDS reads warp-broadcast; results staged (stride 25, conflict-free)
// and written as contiguous 96B runs per batch row.
// ============================================================================
__global__ void __launch_bounds__(256)
forest_kernel(const float* __restrict__ resp,  // (NTREES, UNITS, NLEAVES)
              float* __restrict__ out)         // (BATCH, NTREES, UNITS)
{
    const int nt  = blockIdx.x & 63;      // 64 n-tiles
    const int btl = blockIdx.x >> 6;      // 16 b-tiles
    const int n0  = nt * NT;
    const int b0  = btl * BT;
    const int tid = threadIdx.x;
    const int tx  = tid & 31;             // b_local
    const int ty  = tid >> 5;             // n_local, 0..7

    const int b = b0 + tx;
    const int n = n0 + ty;

    // issue gate loads first (independent of smem staging)
    float g[DEPTH];
    #pragma unroll
    for (int d = 0; d < DEPTH; d++)
        g[d] = g_gate[(n * DEPTH + d) * BATCH + b];

    __shared__ float4 s_resp[NT * 48];            // 8 trees x 192 floats = 6 KB
    __shared__ float  s_out[BT][NT * UNITS + 1];  // 32 x 25, conflict-free

    s_resp[tid] = ((const float4*)resp)[n0 * 48 + tid];
    if (tid < NT * 48 - 256)
        s_resp[tid + 256] = ((const float4*)resp)[n0 * 48 + tid + 256];
    __syncthreads();

    // leaf prob factorization: p_c = qlo[c&7] * qhi[c>>3]
    float qlo[8], qhi[8];
    #pragma unroll
    for (int c = 0; c < 8; c++) {
        float p0 = (c & 1) ? (1.0f - g[0]) : g[0];
        float p1 = (c & 2) ? (1.0f - g[1]) : g[1];
        float p2 = (c & 4) ? (1.0f - g[2]) : g[2];
        qlo[c] = p0 * p1 * p2;
        float p3 = (c & 1) ? (1.0f - g[3]) : g[3];
        float p4 = (c & 2) ? (1.0f - g[4]) : g[4];
        float p5 = (c & 4) ? (1.0f - g[5]) : g[5];
        qhi[c] = p3 * p4 * p5;
    }

    // response contraction (smem reads broadcast across the warp)
    float acc0 = 0.0f, acc1 = 0.0f, acc2 = 0.0f;
    #pragma unroll
    for (int hi = 0; hi < 8; hi++) {
        const float qh = qhi[hi];
        #pragma unroll
        for (int u = 0; u < UNITS; u++) {
            float4 a = s_resp[ty * 48 + (u * NLEAVES + hi * 8) / 4];
            float4 c = s_resp[ty * 48 + (u * NLEAVES + hi * 8) / 4 + 1];
            float t = a.x * qlo[0] + a.y * qlo[1] + a.z * qlo[2] + a.w * qlo[3]
                    + c.x * qlo[4] + c.y * qlo[5] + c.z * qlo[6] + c.w * qlo[7];
            if (u == 0) acc0 += qh * t;
            else if (u == 1) acc1 += qh * t;
            else acc2 += qh * t;
        }
    }

    s_out[tx][ty * UNITS + 0] = acc0;
    s_out[tx][ty * UNITS + 1] = acc1;
    s_out[tx][ty * UNITS + 2] = acc2;
    __syncthreads();

    // coalesced write-out: per-b contiguous 24-float (96 B) runs
    #pragma unroll
    for (int r = 0; r < 3; r++) {
        int i   = tid + r * 256;                 // 0 .. 767
        int row = i / (NT * UNITS);              // b_local
        int c   = i % (NT * UNITS);
        out[(size_t)(b0 + row) * (NTREES * UNITS) + n0 * UNITS + c] = s_out[row][c];
    }
}

// ============================================================================
extern "C" void kernel_launch(void* const* d_in, const int* in_sizes, int n_in,
                              void* d_out, int out_size)
{
    const float* x    = (const float*)d_in[0];  // (512, 256)
    const float* fsl  = (const float*)d_in[1];  // (256, 512, 6)
    const float* th   = (const float*)d_in[2];  // (512, 6)
    const float* lt   = (const float*)d_in[3];  // (512, 6)
    const float* resp = (const float*)d_in[4];  // (512, 3, 64)
    float* out = (float*)d_out;                 // (512, 512, 3)

    transpose_kernel<<<896, 256>>>(x, fsl);
    sparsemax_kernel<<<NCOLS / 8, 256>>>();
    fv_kernel<<<NCOLS, 256>>>(th, lt);
    forest_kernel<<<(BATCH / BT) * (NTREES / NT), 256>>>(resp, out);
}

// round 12
// speedup vs baseline: 1.1966x; 1.0122x over previous
#include <cuda_runtime.h>
#include <cuda_bf16.h>
#include <math.h>

// Problem constants
#define BATCH   512
#define DIM     256
#define NTREES  512
#define DEPTH   6
#define UNITS   3
#define NLEAVES 64
#define NCOLS   (NTREES * DEPTH)   // 3072 sparsemax columns
#define MAXC    64                 // max sparsemax support per column (padded)
#define BT      64                 // forest batch tile (2 b per thread)
#define NT      8                  // forest tree tile

// -------- device scratch (no dynamic allocation allowed) --------
__device__ float  g_xT[DIM * BATCH];       // transposed x: (DIM, BATCH)
__device__ float  g_fslT[NCOLS * DIM];     // transposed fsl: (col, i)
__device__ int    g_nnz[NCOLS];            // PADDED support size (multiple of 8)
__device__ float2 g_sel[NCOLS * MAXC];     // interleaved (idx*BATCH as int bits, weight)
__device__ float  g_gate[NCOLS * BATCH];   // gate values, layout (col, b)

// ============================================================================
// Kernel 0: float4 tiled transposes. 32x32 tiles, 256 threads:
// 1 LDG.128 + 4 STS + 4 LDS + 1 STG.128 per thread, bank-conflict-free.
//  blocks [0, 768): fsl (256 i, 3072 col) -> fslT (col, i).
//  blocks [768, 896): x (512 b, 256 i)    -> xT (i, b).
// ============================================================================
__global__ void __launch_bounds__(256)
transpose_kernel(const float* __restrict__ x,
                 const float* __restrict__ fsl)
{
    __shared__ float s[32][33];
    const int bid = blockIdx.x;
    const int t   = threadIdx.x;
    const int row = t >> 3;       // 0..31 (input row within tile)
    const int c4  = t & 7;        // 0..7  (float4 column within tile)

    const float* src;
    float*       dst;
    int src_stride, dst_stride, r0_in, c0_in;

    if (bid < 768) {
        const int it = bid / 96;          // i-tile (rows of fsl)
        const int ct = bid % 96;          // col-tile
        src = fsl;   src_stride = NCOLS;  r0_in = it * 32; c0_in = ct * 32;
        dst = g_fslT; dst_stride = DIM;
    } else {
        const int tt = bid - 768;
        const int bt = tt & 15;           // b-tile (rows of x)
        const int it = tt >> 4;           // i-tile (cols of x)
        src = x;     src_stride = DIM;    r0_in = bt * 32; c0_in = it * 32;
        dst = g_xT;  dst_stride = BATCH;
    }

    // load: one float4 per thread, write to smem (banks (row+4c4+q)%32: perm)
    float4 v = *(const float4*)(src + (size_t)(r0_in + row) * src_stride + c0_in + c4 * 4);
    s[row][c4 * 4 + 0] = v.x;
    s[row][c4 * 4 + 1] = v.y;
    s[row][c4 * 4 + 2] = v.z;
    s[row][c4 * 4 + 3] = v.w;
    __syncthreads();

    // store: transposed float4 per thread (banks (4c4+q+row)%32: perm)
    float4 w;
    w.x = s[c4 * 4 + 0][row];
    w.y = s[c4 * 4 + 1][row];
    w.z = s[c4 * 4 + 2][row];
    w.w = s[c4 * 4 + 3][row];
    *(float4*)(dst + (size_t)(c0_in + row) * dst_stride + r0_in + c4 * 4) = w;
}

// ============================================================================
// Kernel 1: sparsemax, one warp per column, coalesced fslT loads.
// 384 blocks x 256 threads, warp-level only (no block syncs).
// Michelot warm-started at tau0 = max(z)-1 (valid: tau* >= zmax-1).
// Output list zero-padded to a multiple of 8.
// ============================================================================
__global__ void __launch_bounds__(256)
sparsemax_kernel()
{
    const int warp = threadIdx.x >> 5;
    const int lane = threadIdx.x & 31;
    const int col  = blockIdx.x * 8 + warp;

    float z[8];
    #pragma unroll
    for (int j = 0; j < 8; j++)
        z[j] = g_fslT[col * DIM + j * 32 + lane];

    float m = z[0];
    #pragma unroll
    for (int j = 1; j < 8; j++) m = fmaxf(m, z[j]);
    #pragma unroll
    for (int o = 16; o > 0; o >>= 1)
        m = fmaxf(m, __shfl_xor_sync(0xffffffffu, m, o));
    float tau = m - 1.0f;

    int k_prev = -1;
    #pragma unroll 1
    for (int it = 0; it < 16; it++) {
        float s = 0.0f;
        int   k = 0;
        #pragma unroll
        for (int j = 0; j < 8; j++)
            if (z[j] > tau) { s += z[j]; k++; }
        #pragma unroll
        for (int o = 16; o > 0; o >>= 1)
            s += __shfl_xor_sync(0xffffffffu, s, o);
        k = __reduce_add_sync(0xffffffffu, k);
        if (k == k_prev) break;
        k_prev = k;
        tau = (s - 1.0f) / (float)k;
    }

    int base = 0;
    #pragma unroll
    for (int j = 0; j < 8; j++) {
        const bool nz = (z[j] > tau);
        const unsigned mm = __ballot_sync(0xffffffffu, nz);
        if (nz) {
            int pos = base + __popc(mm & ((1u << lane) - 1u));
            if (pos < MAXC)
                g_sel[col * MAXC + pos] =
                    make_float2(__int_as_float((j * 32 + lane) * BATCH), z[j] - tau);
        }
        base += __popc(mm);
    }
    if (base > MAXC) base = MAXC;
    const int pad = (base + 7) & ~7;
    if (lane < pad - base)
        g_sel[col * MAXC + base + lane] = make_float2(__int_as_float(0), 0.0f);
    if (lane == 0) g_nnz[col] = pad;
}

// ============================================================================
// Kernel 2: gate[col][b] = sparsemoid((sum_j w_j*xT[idx_j][b] - th)*e^{-lt}).
// One block per column (3072 blocks, 256 threads, 2 b's per thread).
// Branchless 8-entry steps: 16 independent xT loads in flight.
// ============================================================================
__global__ void __launch_bounds__(256)
fv_kernel(const float* __restrict__ th,
          const float* __restrict__ lt)
{
    const int col = blockIdx.x;
    const int tid = threadIdx.x;
    const int cnt = g_nnz[col];           // multiple of 8
    const float2* __restrict__ lst = g_sel + col * MAXC;

    const float thv = __ldg(th + col);
    const float etv = __expf(-__ldg(lt + col));

    float f0 = 0.0f, f1 = 0.0f;
    #pragma unroll 1
    for (int j = 0; j < cnt; j += 8) {
        float2 e[8];
        #pragma unroll
        for (int q = 0; q < 8; q++) e[q] = __ldg(lst + j + q);
        float v0[8], v1[8];
        #pragma unroll
        for (int q = 0; q < 8; q++) {
            int o = __float_as_int(e[q].x);
            v0[q] = g_xT[o + tid];
            v1[q] = g_xT[o + tid + 256];
        }
        #pragma unroll
        for (int q = 0; q < 8; q++) {
            f0 += e[q].y * v0[q];
            f1 += e[q].y * v1[q];
        }
    }
    g_gate[col * BATCH + tid]       = __saturatef(0.5f * ((f0 - thv) * etv) + 0.5f);
    g_gate[col * BATCH + tid + 256] = __saturatef(0.5f * ((f1 - thv) * etv) + 0.5f);
}

// ============================================================================
// Kernel 3: tiled forest, 2 batch rows per thread, coalesced output.
// Block = (64-b x 8-n) tile; 512 blocks x 256 threads, forced 4 blocks/SM
// (single wave). Each resp float4 LDS feeds BOTH b's -> resp LDS amortized 2x.
// ============================================================================
__global__ void __launch_bounds__(256, 4)
forest_kernel(const float* __restrict__ resp,  // (NTREES, UNITS, NLEAVES)
              float* __restrict__ out)         // (BATCH, NTREES, UNITS)
{
    const int nt  = blockIdx.x & 63;      // 64 n-tiles
    const int btl = blockIdx.x >> 6;      // 8 b-tiles
    const int n0  = nt * NT;
    const int b0  = btl * BT;
    const int tid = threadIdx.x;
    const int tx  = tid & 31;             // b_local (first of two)
    const int ty  = tid >> 5;             // n_local, 0..7

    const int b1 = b0 + tx;
    const int n  = n0 + ty;

    // issue all gate loads first (independent of smem staging)
    float ga[DEPTH], gb[DEPTH];
    #pragma unroll
    for (int d = 0; d < DEPTH; d++) {
        ga[d] = g_gate[(n * DEPTH + d) * BATCH + b1];
        gb[d] = g_gate[(n * DEPTH + d) * BATCH + b1 + 32];
    }

    __shared__ float4 s_resp[NT * 48];            // 8 trees x 192 floats = 6 KB
    __shared__ float  s_out[BT][NT * UNITS + 1];  // 64 x 25, conflict-free

    s_resp[tid] = ((const float4*)resp)[n0 * 48 + tid];
    if (tid < NT * 48 - 256)
        s_resp[tid + 256] = ((const float4*)resp)[n0 * 48 + tid + 256];
    __syncthreads();

    // leaf prob factorization for both b's: p_c = qlo[c&7] * qhi[c>>3]
    float qloa[8], qhia[8], qlob[8], qhib[8];
    #pragma unroll
    for (int c = 0; c < 8; c++) {
        float a0 = (c & 1) ? (1.0f - ga[0]) : ga[0];
        float a1 = (c & 2) ? (1.0f - ga[1]) : ga[1];
        float a2 = (c & 4) ? (1.0f - ga[2]) : ga[2];
        qloa[c] = a0 * a1 * a2;
        float a3 = (c & 1) ? (1.0f - ga[3]) : ga[3];
        float a4 = (c & 2) ? (1.0f - ga[4]) : ga[4];
        float a5 = (c & 4) ? (1.0f - ga[5]) : ga[5];
        qhia[c] = a3 * a4 * a5;
        float b0_ = (c & 1) ? (1.0f - gb[0]) : gb[0];
        float b1_ = (c & 2) ? (1.0f - gb[1]) : gb[1];
        float b2_ = (c & 4) ? (1.0f - gb[2]) : gb[2];
        qlob[c] = b0_ * b1_ * b2_;
        float b3_ = (c & 1) ? (1.0f - gb[3]) : gb[3];
        float b4_ = (c & 2) ? (1.0f - gb[4]) : gb[4];
        float b5_ = (c & 4) ? (1.0f - gb[5]) : gb[5];
        qhib[c] = b3_ * b4_ * b5_;
    }

    // response contraction: each resp float4 used by BOTH b's
    float acca[UNITS] = {0.0f, 0.0f, 0.0f};
    float accb[UNITS] = {0.0f, 0.0f, 0.0f};
    #pragma unroll
    for (int hi = 0; hi < 8; hi++) {
        #pragma unroll
        for (int u = 0; u < UNITS; u++) {
            float4 ra = s_resp[ty * 48 + (u * NLEAVES + hi * 8) / 4];
            float4 rc = s_resp[ty * 48 + (u * NLEAVES + hi * 8) / 4 + 1];
            float t1 = ra.x * qloa[0] + ra.y * qloa[1] + ra.z * qloa[2] + ra.w * qloa[3]
                     + rc.x * qloa[4] + rc.y * qloa[5] + rc.z * qloa[6] + rc.w * qloa[7];
            float t2 = ra.x * qlob[0] + ra.y * qlob[1] + ra.z * qlob[2] + ra.w * qlob[3]
                     + rc.x * qlob[4] + rc.y * qlob[5] + rc.z * qlob[6] + rc.w * qlob[7];
            acca[u] += qhia[hi] * t1;
            accb[u] += qhib[hi] * t2;
        }
    }

    #pragma unroll
    for (int u = 0; u < UNITS; u++) {
        s_out[tx][ty * UNITS + u]      = acca[u];
        s_out[tx + 32][ty * UNITS + u] = accb[u];
    }
    __syncthreads();

    // coalesced write-out: per-b contiguous 24-float (96 B) runs
    #pragma unroll
    for (int r = 0; r < 6; r++) {
        int i   = tid + r * 256;                 // 0 .. 1535
        int row = i / (NT * UNITS);              // b_local 0..63
        int c   = i % (NT * UNITS);
        out[(size_t)(b0 + row) * (NTREES * UNITS) + n0 * UNITS + c] = s_out[row][c];
    }
}

// ============================================================================
extern "C" void kernel_launch(void* const* d_in, const int* in_sizes, int n_in,
                              void* d_out, int out_size)
{
    const float* x    = (const float*)d_in[0];  // (512, 256)
    const float* fsl  = (const float*)d_in[1];  // (256, 512, 6)
    const float* th   = (const float*)d_in[2];  // (512, 6)
    const float* lt   = (const float*)d_in[3];  // (512, 6)
    const float* resp = (const float*)d_in[4];  // (512, 3, 64)
    float* out = (float*)d_out;                 // (512, 512, 3)

    transpose_kernel<<<896, 256>>>(x, fsl);
    sparsemax_kernel<<<NCOLS / 8, 256>>>();
    fv_kernel<<<NCOLS, 256>>>(th, lt);
    forest_kernel<<<(BATCH / BT) * (NTREES / NT), 256>>>(resp, out);
}